// round 16
// baseline (speedup 1.0000x reference)
#include <cuda_runtime.h>

#define HIDDEN 2048
#define HEADS  16
#define HDIM   128
#define BATCH  4
#define SEQ    2048
#define MROWS  (BATCH*SEQ)        /* 8192 */
#define NQKV   (3*HIDDEN)         /* 6144 */

// ---------------- scratch (device globals; no runtime allocation) ----------
__device__ float g_qkv[(size_t)MROWS * NQKV];                 // 201 MB
__device__ float g_q  [(size_t)BATCH*HEADS*SEQ*HDIM];         // 67 MB  [B,H,L,D]
__device__ float g_k  [(size_t)BATCH*HEADS*SEQ*HDIM];
__device__ float g_v  [(size_t)BATCH*HEADS*SEQ*HDIM];
__device__ float g_ao [(size_t)MROWS * HIDDEN];               // [B,L,H*D]

// ============================================================================
// SGEMM (NT): C[m][n] = sum_k A[m*K+k] * B[n*K+k]
// 128x128 block tile, BK=16, 256 threads, 8x8 per-thread register tile.
// Both A and B tiles stored k-major-transposed in smem: s[kk][row].
// Requires M%128==0, N%128==0, K%16==0 (true for all our shapes).
// ============================================================================
__global__ __launch_bounds__(256, 2)
void sgemm_nt(const float* __restrict__ A, const float* __restrict__ B,
              float* __restrict__ C, int M, int N, int K)
{
    __shared__ float As[16 * 128];
    __shared__ float Bs[16 * 128];

    const int tid = threadIdx.x;
    const int ty  = tid >> 4;      // 0..15
    const int tx  = tid & 15;      // 0..15
    const int m0  = blockIdx.y * 128;
    const int n0  = blockIdx.x * 128;

    float acc[8][8];
#pragma unroll
    for (int i = 0; i < 8; ++i)
#pragma unroll
        for (int j = 0; j < 8; ++j) acc[i][j] = 0.f;

    for (int k0 = 0; k0 < K; k0 += 16) {
        // cooperative load: tile is [128 rows][16 k]; 512 float4 per tensor
#pragma unroll
        for (int t = 0; t < 2; ++t) {
            int idx = tid * 2 + t;
            int row = idx >> 2;
            int kq  = idx & 3;
            float4 av = *(const float4*)(A + (size_t)(m0 + row) * K + k0 + kq * 4);
            float4 bv = *(const float4*)(B + (size_t)(n0 + row) * K + k0 + kq * 4);
            As[(kq*4+0)*128 + row] = av.x; As[(kq*4+1)*128 + row] = av.y;
            As[(kq*4+2)*128 + row] = av.z; As[(kq*4+3)*128 + row] = av.w;
            Bs[(kq*4+0)*128 + row] = bv.x; Bs[(kq*4+1)*128 + row] = bv.y;
            Bs[(kq*4+2)*128 + row] = bv.z; Bs[(kq*4+3)*128 + row] = bv.w;
        }
        __syncthreads();
#pragma unroll
        for (int kk = 0; kk < 16; ++kk) {
            float4 a0 = *(const float4*)(As + kk*128 + ty*4);
            float4 a1 = *(const float4*)(As + kk*128 + 64 + ty*4);
            float4 b0 = *(const float4*)(Bs + kk*128 + tx*4);
            float4 b1 = *(const float4*)(Bs + kk*128 + 64 + tx*4);
            float av[8] = {a0.x,a0.y,a0.z,a0.w,a1.x,a1.y,a1.z,a1.w};
            float bv[8] = {b0.x,b0.y,b0.z,b0.w,b1.x,b1.y,b1.z,b1.w};
#pragma unroll
            for (int i = 0; i < 8; ++i)
#pragma unroll
                for (int j = 0; j < 8; ++j)
                    acc[i][j] += av[i] * bv[j];
        }
        __syncthreads();
    }

#pragma unroll
    for (int i = 0; i < 8; ++i) {
        int r = m0 + ((i < 4) ? (ty*4 + i) : (60 + ty*4 + i));  // i>=4 -> 64+ty*4+(i-4)
#pragma unroll
        for (int jg = 0; jg < 2; ++jg) {
            float4 v = make_float4(acc[i][jg*4+0], acc[i][jg*4+1],
                                   acc[i][jg*4+2], acc[i][jg*4+3]);
            *(float4*)(C + (size_t)r * N + n0 + jg*64 + tx*4) = v;
        }
    }
}

// ============================================================================
// RoPE + split qkv[B,L,3*HIDDEN] -> Q,K (rotated), V  in [B,H,L,D]
// One thread per (b,h,l,d0) with d0 in [0,64): handles the paired element too.
// ============================================================================
__global__ __launch_bounds__(256)
void rope_split(const float* __restrict__ qkv,
                const float* __restrict__ cs, const float* __restrict__ sn,
                float* __restrict__ Q, float* __restrict__ Kd,
                float* __restrict__ V)
{
    int idx = blockIdx.x * blockDim.x + threadIdx.x;     // B*L*H*64 threads
    int d0 = idx & 63;
    int h  = (idx >> 6) & 15;
    int l  = (idx >> 10) & 2047;
    int b  = idx >> 21;

    const float* row = qkv + (size_t)(b * SEQ + l) * NQKV;
    float c0 = cs[l*HDIM + d0],      s0 = sn[l*HDIM + d0];
    float c1 = cs[l*HDIM + d0 + 64], s1 = sn[l*HDIM + d0 + 64];

    size_t obase = ((size_t)((b*HEADS + h) * SEQ + l)) * HDIM;

    float q0 = row[h*HDIM + d0], q1 = row[h*HDIM + d0 + 64];
    Q[obase + d0]      = q0 * c0 - q1 * s0;
    Q[obase + d0 + 64] = q1 * c1 + q0 * s1;

    float k0 = row[HIDDEN + h*HDIM + d0], k1 = row[HIDDEN + h*HDIM + d0 + 64];
    Kd[obase + d0]      = k0 * c0 - k1 * s0;
    Kd[obase + d0 + 64] = k1 * c1 + k0 * s1;

    V[obase + d0]      = row[2*HIDDEN + h*HDIM + d0];
    V[obase + d0 + 64] = row[2*HIDDEN + h*HDIM + d0 + 64];
}

// ============================================================================
// Flash attention, fp32. grid = (SEQ/128, B*H), 256 threads.
// Q tile 128 rows, KV tile 128 rows, D=128 streamed with BK=16 for S = Q K^T.
// Online softmax; P staged transposed in smem (pitch 132 to cut STS conflicts);
// O = P V accumulated in registers (8x8/thread). Output written in [B,L,H,D].
// Dynamic smem = 149504 B.
// ============================================================================
#define PS_PITCH 132
#define ATT_SMEM ((2*16*128 + 128*PS_PITCH + 128*128) * 4)

__global__ __launch_bounds__(256)
void attn_kernel(const float* __restrict__ Q, const float* __restrict__ K,
                 const float* __restrict__ V, float* __restrict__ AO)
{
    extern __shared__ float sm[];
    float* As = sm;                       // [16][128]  Q d-slice, transposed
    float* Bs = As + 16*128;              // [16][128]  K d-slice, transposed
    float* Ps = Bs + 16*128;              // [128][132] P transposed: Ps[k][r]
    float* Vs = Ps + 128*PS_PITCH;        // [128][128] V tile: Vs[k][c]

    const int bh = blockIdx.y;
    const int qt = blockIdx.x;
    const float* Qp = Q + (size_t)bh * SEQ * HDIM + (size_t)qt * 128 * HDIM;
    const float* Kp = K + (size_t)bh * SEQ * HDIM;
    const float* Vp = V + (size_t)bh * SEQ * HDIM;

    const int tid = threadIdx.x;
    const int ty  = tid >> 4;
    const int tx  = tid & 15;

    const float scale = 0.08838834764831845f;   // 1/sqrt(128)

    float m[8], l[8], o[8][8];
#pragma unroll
    for (int i = 0; i < 8; ++i) {
        m[i] = -1e30f; l[i] = 0.f;
#pragma unroll
        for (int j = 0; j < 8; ++j) o[i][j] = 0.f;
    }

    for (int kt = 0; kt < SEQ; kt += 128) {
        // ---------------- S = Q K^T (this 128x128 tile) ----------------
        float s[8][8];
#pragma unroll
        for (int i = 0; i < 8; ++i)
#pragma unroll
            for (int j = 0; j < 8; ++j) s[i][j] = 0.f;

        for (int d0 = 0; d0 < HDIM; d0 += 16) {
#pragma unroll
            for (int t = 0; t < 2; ++t) {
                int idx = tid * 2 + t;
                int row = idx >> 2;
                int kq  = idx & 3;
                float4 qa = *(const float4*)(Qp + (size_t)row * HDIM + d0 + kq*4);
                float4 kb = *(const float4*)(Kp + (size_t)(kt + row) * HDIM + d0 + kq*4);
                As[(kq*4+0)*128 + row] = qa.x; As[(kq*4+1)*128 + row] = qa.y;
                As[(kq*4+2)*128 + row] = qa.z; As[(kq*4+3)*128 + row] = qa.w;
                Bs[(kq*4+0)*128 + row] = kb.x; Bs[(kq*4+1)*128 + row] = kb.y;
                Bs[(kq*4+2)*128 + row] = kb.z; Bs[(kq*4+3)*128 + row] = kb.w;
            }
            __syncthreads();
#pragma unroll
            for (int kk = 0; kk < 16; ++kk) {
                float4 a0 = *(const float4*)(As + kk*128 + ty*4);
                float4 a1 = *(const float4*)(As + kk*128 + 64 + ty*4);
                float4 b0 = *(const float4*)(Bs + kk*128 + tx*4);
                float4 b1 = *(const float4*)(Bs + kk*128 + 64 + tx*4);
                float av[8] = {a0.x,a0.y,a0.z,a0.w,a1.x,a1.y,a1.z,a1.w};
                float bv[8] = {b0.x,b0.y,b0.z,b0.w,b1.x,b1.y,b1.z,b1.w};
#pragma unroll
                for (int i = 0; i < 8; ++i)
#pragma unroll
                    for (int j = 0; j < 8; ++j)
                        s[i][j] += av[i] * bv[j];
            }
            __syncthreads();
        }

        // ---------------- online softmax (rows owned by ty; reduce over tx) --
#pragma unroll
        for (int i = 0; i < 8; ++i) {
            float rmax = -1e30f;
#pragma unroll
            for (int j = 0; j < 8; ++j) { s[i][j] *= scale; rmax = fmaxf(rmax, s[i][j]); }
#pragma unroll
            for (int off = 8; off > 0; off >>= 1)
                rmax = fmaxf(rmax, __shfl_xor_sync(0xffffffffu, rmax, off, 16));
            float mnew = fmaxf(m[i], rmax);
            float corr = __expf(m[i] - mnew);
            float rsum = 0.f;
#pragma unroll
            for (int j = 0; j < 8; ++j) { s[i][j] = __expf(s[i][j] - mnew); rsum += s[i][j]; }
#pragma unroll
            for (int off = 8; off > 0; off >>= 1)
                rsum += __shfl_xor_sync(0xffffffffu, rsum, off, 16);
            m[i] = mnew;
            l[i] = l[i] * corr + rsum;
#pragma unroll
            for (int j = 0; j < 8; ++j) o[i][j] *= corr;
        }

        // ---------------- stage P^T to smem + load V tile ----------------
#pragma unroll
        for (int jj = 0; jj < 8; ++jj) {
            int c = (jj < 4) ? (tx*4 + jj) : (60 + tx*4 + jj);
            float4 p0 = make_float4(s[0][jj], s[1][jj], s[2][jj], s[3][jj]);
            float4 p1 = make_float4(s[4][jj], s[5][jj], s[6][jj], s[7][jj]);
            *(float4*)(Ps + c*PS_PITCH + ty*4)      = p0;
            *(float4*)(Ps + c*PS_PITCH + 64 + ty*4) = p1;
        }
#pragma unroll
        for (int t = 0; t < 16; ++t) {                 // 4096 float4 / 256 thr
            int idx = t * 256 + tid;
            int row = idx >> 5;
            int cq  = idx & 31;
            *(float4*)(Vs + row*128 + cq*4) =
                *(const float4*)(Vp + (size_t)(kt + row) * HDIM + cq*4);
        }
        __syncthreads();

        // ---------------- O += P V ----------------
#pragma unroll 4
        for (int kk = 0; kk < 128; ++kk) {
            float4 a0 = *(const float4*)(Ps + kk*PS_PITCH + ty*4);
            float4 a1 = *(const float4*)(Ps + kk*PS_PITCH + 64 + ty*4);
            float4 b0 = *(const float4*)(Vs + kk*128 + tx*4);
            float4 b1 = *(const float4*)(Vs + kk*128 + 64 + tx*4);
            float av[8] = {a0.x,a0.y,a0.z,a0.w,a1.x,a1.y,a1.z,a1.w};
            float bv[8] = {b0.x,b0.y,b0.z,b0.w,b1.x,b1.y,b1.z,b1.w};
#pragma unroll
            for (int i = 0; i < 8; ++i)
#pragma unroll
                for (int j = 0; j < 8; ++j)
                    o[i][j] += av[i] * bv[j];
        }
        __syncthreads();
    }

    // ---------------- finalize & write to [B, L, H, D] ----------------
    const int b = bh >> 4, h = bh & 15;
#pragma unroll
    for (int i = 0; i < 8; ++i) {
        int rloc = (i < 4) ? (ty*4 + i) : (60 + ty*4 + i);
        int lg = qt * 128 + rloc;
        float inv = 1.f / l[i];
        size_t base = ((size_t)((b * SEQ + lg) * HEADS + h)) * HDIM;
#pragma unroll
        for (int jg = 0; jg < 2; ++jg) {
            float4 v4 = make_float4(o[i][jg*4+0]*inv, o[i][jg*4+1]*inv,
                                    o[i][jg*4+2]*inv, o[i][jg*4+3]*inv);
            *(float4*)(AO + base + jg*64 + tx*4) = v4;
        }
    }
}

// ============================================================================
// launch
// ============================================================================
extern "C" void kernel_launch(void* const* d_in, const int* in_sizes, int n_in,
                              void* d_out, int out_size)
{
    (void)in_sizes; (void)n_in; (void)out_size;
    const float* x    = (const float*)d_in[0];
    const float* cs   = (const float*)d_in[1];
    const float* sn   = (const float*)d_in[2];
    const float* wqkv = (const float*)d_in[3];
    const float* wout = (const float*)d_in[4];
    float* out = (float*)d_out;

    float *qkv, *q, *k, *v, *ao;
    cudaGetSymbolAddress((void**)&qkv, g_qkv);
    cudaGetSymbolAddress((void**)&q,   g_q);
    cudaGetSymbolAddress((void**)&k,   g_k);
    cudaGetSymbolAddress((void**)&v,   g_v);
    cudaGetSymbolAddress((void**)&ao,  g_ao);

    cudaFuncSetAttribute(attn_kernel,
                         cudaFuncAttributeMaxDynamicSharedMemorySize, ATT_SMEM);

    dim3 blk(256);
    // 1) qkv = x @ w_qkv^T   [8192, 6144]
    sgemm_nt<<<dim3(NQKV/128, MROWS/128), blk>>>(x, wqkv, qkv, MROWS, NQKV, HIDDEN);
    // 2) RoPE + split to [B,H,L,D]
    rope_split<<<(BATCH*SEQ*HEADS*64)/256, blk>>>(qkv, cs, sn, q, k, v);
    // 3) attention -> [B,L,H*D]
    attn_kernel<<<dim3(SEQ/128, BATCH*HEADS), blk, ATT_SMEM>>>(q, k, v, ao);
    // 4) out = ao @ w_out^T
    sgemm_nt<<<dim3(HIDDEN/128, MROWS/128), blk>>>(ao, wout, out, MROWS, HIDDEN, HIDDEN);
}

// round 17
// speedup vs baseline: 2.9768x; 2.9768x over previous
#include <cuda_runtime.h>

#define HIDDEN 2048
#define HEADS  16
#define HDIM   128
#define BATCH  4
#define SEQ    2048
#define MROWS  (BATCH*SEQ)        /* 8192 */
#define NQKV   (3*HIDDEN)         /* 6144 */

// ---------------- scratch (device globals; no runtime allocation) ----------
__device__ float g_qkv[(size_t)MROWS * NQKV];                 // 201 MB
__device__ float g_q  [(size_t)BATCH*HEADS*SEQ*HDIM];         // [B,H,L,D]
__device__ float g_k  [(size_t)BATCH*HEADS*SEQ*HDIM];
__device__ float g_vt [(size_t)BATCH*HEADS*HDIM*SEQ];         // [B,H,D,L] (transposed)
__device__ float g_ao [(size_t)MROWS * HIDDEN];               // [B,L,H*D]

// ---------------- tf32 helpers ----------------
__device__ __forceinline__ unsigned f2tf(float f) {
    unsigned u; asm("cvt.rna.tf32.f32 %0, %1;" : "=r"(u) : "f"(f)); return u;
}
__device__ __forceinline__ void mma8(float* d, const unsigned* a, const unsigned* b) {
    asm("mma.sync.aligned.m16n8k8.row.col.f32.tf32.tf32.f32 "
        "{%0,%1,%2,%3}, {%4,%5,%6,%7}, {%8,%9}, {%0,%1,%2,%3};"
        : "+f"(d[0]), "+f"(d[1]), "+f"(d[2]), "+f"(d[3])
        : "r"(a[0]), "r"(a[1]), "r"(a[2]), "r"(a[3]), "r"(b[0]), "r"(b[1]));
}

// ============================================================================
// TF32 GEMM (NT): C[m][n] = sum_k A[m*K+k] * B[n*K+k]
// 128x128 block, BK=32, 8 warps (4x2), warp tile 32x64 of m16n8k8 mmas.
// Smem layout [row][k] pitch 36: fragment LDS addr mod 32 = 4*(lane/4)+lane%4
// (+const) -> conflict-free.
// ============================================================================
__global__ __launch_bounds__(256, 2)
void gemm_tf32(const float* __restrict__ A, const float* __restrict__ B,
               float* __restrict__ C, int M, int N, int K)
{
    __shared__ unsigned As[128 * 36];
    __shared__ unsigned Bs[128 * 36];

    const int tid = threadIdx.x, lane = tid & 31, wid = tid >> 5;
    const int wm = wid >> 1, wn = wid & 1;
    const int g = lane >> 2, q = lane & 3;
    const int m0 = blockIdx.y * 128, n0 = blockIdx.x * 128;

    float acc[2][8][4];
#pragma unroll
    for (int i = 0; i < 2; ++i)
#pragma unroll
        for (int j = 0; j < 8; ++j)
#pragma unroll
            for (int p = 0; p < 4; ++p) acc[i][j][p] = 0.f;

    for (int k0 = 0; k0 < K; k0 += 32) {
#pragma unroll
        for (int j = 0; j < 4; ++j) {
            int t2 = tid + 256 * j;
            int row = t2 >> 3, qq = t2 & 7;
            float4 a4 = *(const float4*)(A + (size_t)(m0 + row) * K + k0 + qq * 4);
            float4 b4 = *(const float4*)(B + (size_t)(n0 + row) * K + k0 + qq * 4);
            *(uint4*)(As + row * 36 + qq * 4) =
                make_uint4(f2tf(a4.x), f2tf(a4.y), f2tf(a4.z), f2tf(a4.w));
            *(uint4*)(Bs + row * 36 + qq * 4) =
                make_uint4(f2tf(b4.x), f2tf(b4.y), f2tf(b4.z), f2tf(b4.w));
        }
        __syncthreads();
#pragma unroll
        for (int ks = 0; ks < 4; ++ks) {
            const int kb = ks * 8;
            unsigned af[2][4], bf[8][2];
#pragma unroll
            for (int i = 0; i < 2; ++i) {
                int r = (wm * 32 + i * 16 + g) * 36 + kb + q;
                af[i][0] = As[r];           af[i][1] = As[r + 8 * 36];
                af[i][2] = As[r + 4];       af[i][3] = As[r + 8 * 36 + 4];
            }
#pragma unroll
            for (int j = 0; j < 8; ++j) {
                int r = (wn * 64 + j * 8 + g) * 36 + kb + q;
                bf[j][0] = Bs[r];           bf[j][1] = Bs[r + 4];
            }
#pragma unroll
            for (int i = 0; i < 2; ++i)
#pragma unroll
                for (int j = 0; j < 8; ++j) mma8(acc[i][j], af[i], bf[j]);
        }
        __syncthreads();
    }

#pragma unroll
    for (int i = 0; i < 2; ++i) {
        int r = m0 + wm * 32 + i * 16 + g;
#pragma unroll
        for (int j = 0; j < 8; ++j) {
            int c = n0 + wn * 64 + j * 8 + 2 * q;
            *(float2*)(C + (size_t)r * N + c) =
                make_float2(acc[i][j][0], acc[i][j][1]);
            *(float2*)(C + (size_t)(r + 8) * N + c) =
                make_float2(acc[i][j][2], acc[i][j][3]);
        }
    }
}

// ============================================================================
// RoPE + split qkv -> Q, K in [B,H,L,D] (V handled by transpose_v)
// ============================================================================
__global__ __launch_bounds__(256)
void rope_split(const float* __restrict__ qkv,
                const float* __restrict__ cs, const float* __restrict__ sn,
                float* __restrict__ Q, float* __restrict__ Kd)
{
    int idx = blockIdx.x * blockDim.x + threadIdx.x;
    int d0 = idx & 63;
    int h  = (idx >> 6) & 15;
    int l  = (idx >> 10) & 2047;
    int b  = idx >> 21;

    const float* row = qkv + (size_t)(b * SEQ + l) * NQKV;
    float c0 = cs[l*HDIM + d0],      s0 = sn[l*HDIM + d0];
    float c1 = cs[l*HDIM + d0 + 64], s1 = sn[l*HDIM + d0 + 64];

    size_t obase = ((size_t)((b*HEADS + h) * SEQ + l)) * HDIM;

    float q0 = row[h*HDIM + d0], q1 = row[h*HDIM + d0 + 64];
    Q[obase + d0]      = q0 * c0 - q1 * s0;
    Q[obase + d0 + 64] = q1 * c1 + q0 * s1;

    float k0 = row[HIDDEN + h*HDIM + d0], k1 = row[HIDDEN + h*HDIM + d0 + 64];
    Kd[obase + d0]      = k0 * c0 - k1 * s0;
    Kd[obase + d0 + 64] = k1 * c1 + k0 * s1;
}

// ============================================================================
// V transpose: qkv[b,l, 2H + hd] -> Vt[b, hd, l]  (tiled, coalesced both sides)
// grid (SEQ/32, HIDDEN/32, B), block (32, 8)
// ============================================================================
__global__ __launch_bounds__(256)
void transpose_v(const float* __restrict__ qkv, float* __restrict__ Vt)
{
    __shared__ float t[32][33];
    int b = blockIdx.z;
    int l0 = blockIdx.x * 32, c0 = blockIdx.y * 32;
    int tx = threadIdx.x, ty = threadIdx.y;
#pragma unroll
    for (int r = 0; r < 4; ++r)
        t[ty + 8*r][tx] =
            qkv[(size_t)(b * SEQ + l0 + ty + 8*r) * NQKV + 2*HIDDEN + c0 + tx];
    __syncthreads();
#pragma unroll
    for (int r = 0; r < 4; ++r)
        Vt[(size_t)(b * HIDDEN + c0 + ty + 8*r) * SEQ + l0 + tx] = t[tx][ty + 8*r];
}

// ============================================================================
// TF32 flash attention. grid = (SEQ/128, B*H), 256 threads (8 warps, 4x2).
// Q tile resident (prescaled), K and V share one smem buffer, P restaged as
// tf32 in smem, cross-warp softmax via redM/redL.
// Dynamic smem = 3*128*132*4 + 2048 = 204800 B.
// ============================================================================
#define AP 132
#define ATT_SMEM (3 * 128 * AP * 4 + 2 * 2 * 128 * 4)

__global__ __launch_bounds__(256)
void attn_tf32(const float* __restrict__ Q, const float* __restrict__ K,
               const float* __restrict__ Vt, float* __restrict__ AO)
{
    extern __shared__ unsigned sm[];
    unsigned* Qs  = sm;                   // [128][132] Q (tf32, prescaled)
    unsigned* KVs = Qs + 128 * AP;        // [128][132] K rows, then V^T rows (d)
    unsigned* Ps  = KVs + 128 * AP;       // [128][132] P (tf32), row-major m x k
    float* redM = (float*)(Ps + 128 * AP);   // [2][128]
    float* redL = redM + 256;                // [2][128]

    const int tid = threadIdx.x, lane = tid & 31, wid = tid >> 5;
    const int wm = wid >> 1, wn = wid & 1;
    const int g = lane >> 2, q = lane & 3;
    const int bh = blockIdx.y, qt = blockIdx.x;
    const float scale = 0.08838834764831845f;  // 1/sqrt(128)

    const float* Qp = Q  + (size_t)bh * SEQ * HDIM + (size_t)qt * 128 * HDIM;
    const float* Kp = K  + (size_t)bh * SEQ * HDIM;
    const float* Vp = Vt + (size_t)bh * HDIM * SEQ;

    // stage Q once, prescaled
#pragma unroll
    for (int j = 0; j < 16; ++j) {
        int row = (tid >> 5) + 8 * j, qq = tid & 31;
        float4 v = *(const float4*)(Qp + (size_t)row * HDIM + qq * 4);
        *(uint4*)(Qs + row * AP + qq * 4) =
            make_uint4(f2tf(v.x*scale), f2tf(v.y*scale), f2tf(v.z*scale), f2tf(v.w*scale));
    }

    float mrow[4], lrow[4], o[2][8][4];
#pragma unroll
    for (int t = 0; t < 4; ++t) { mrow[t] = -1e30f; lrow[t] = 0.f; }
#pragma unroll
    for (int i = 0; i < 2; ++i)
#pragma unroll
        for (int j = 0; j < 8; ++j)
#pragma unroll
            for (int p = 0; p < 4; ++p) o[i][j][p] = 0.f;

    for (int kt = 0; kt < SEQ; kt += 128) {
        // ---- stage K tile ----
#pragma unroll
        for (int j = 0; j < 16; ++j) {
            int row = (tid >> 5) + 8 * j, qq = tid & 31;
            float4 v = *(const float4*)(Kp + (size_t)(kt + row) * HDIM + qq * 4);
            *(uint4*)(KVs + row * AP + qq * 4) =
                make_uint4(f2tf(v.x), f2tf(v.y), f2tf(v.z), f2tf(v.w));
        }
        __syncthreads();

        // ---- S = Q K^T (prescaled) ----
        float s[2][8][4];
#pragma unroll
        for (int i = 0; i < 2; ++i)
#pragma unroll
            for (int j = 0; j < 8; ++j)
#pragma unroll
                for (int p = 0; p < 4; ++p) s[i][j][p] = 0.f;
#pragma unroll
        for (int ks = 0; ks < 16; ++ks) {
            const int kb = ks * 8;
            unsigned af[2][4], bf[8][2];
#pragma unroll
            for (int i = 0; i < 2; ++i) {
                int r = (wm * 32 + i * 16 + g) * AP + kb + q;
                af[i][0] = Qs[r];       af[i][1] = Qs[r + 8 * AP];
                af[i][2] = Qs[r + 4];   af[i][3] = Qs[r + 8 * AP + 4];
            }
#pragma unroll
            for (int j = 0; j < 8; ++j) {
                int r = (wn * 64 + j * 8 + g) * AP + kb + q;
                bf[j][0] = KVs[r];      bf[j][1] = KVs[r + 4];
            }
#pragma unroll
            for (int i = 0; i < 2; ++i)
#pragma unroll
                for (int j = 0; j < 8; ++j) mma8(s[i][j], af[i], bf[j]);
        }

        // ---- online softmax: per-warp partial rowmax ----
        float mx[4];
#pragma unroll
        for (int t = 0; t < 4; ++t) mx[t] = -1e30f;
#pragma unroll
        for (int i = 0; i < 2; ++i)
#pragma unroll
            for (int j = 0; j < 8; ++j) {
                mx[2*i]   = fmaxf(mx[2*i],   fmaxf(s[i][j][0], s[i][j][1]));
                mx[2*i+1] = fmaxf(mx[2*i+1], fmaxf(s[i][j][2], s[i][j][3]));
            }
#pragma unroll
        for (int t = 0; t < 4; ++t) {
            mx[t] = fmaxf(mx[t], __shfl_xor_sync(0xffffffffu, mx[t], 1));
            mx[t] = fmaxf(mx[t], __shfl_xor_sync(0xffffffffu, mx[t], 2));
        }
        if (q == 0) {
#pragma unroll
            for (int t = 0; t < 4; ++t)
                redM[wn * 128 + wm * 32 + t * 8 + g] = mx[t];
        }
        __syncthreads();

        float corr[4], sum[4];
#pragma unroll
        for (int t = 0; t < 4; ++t) {
            int r = wm * 32 + t * 8 + g;
            float full = fmaxf(redM[r], redM[128 + r]);
            float mnew = fmaxf(mrow[t], full);
            corr[t] = __expf(mrow[t] - mnew);
            mrow[t] = mnew; sum[t] = 0.f;
        }
#pragma unroll
        for (int i = 0; i < 2; ++i)
#pragma unroll
            for (int j = 0; j < 8; ++j) {
                s[i][j][0] = __expf(s[i][j][0] - mrow[2*i]);   sum[2*i]   += s[i][j][0];
                s[i][j][1] = __expf(s[i][j][1] - mrow[2*i]);   sum[2*i]   += s[i][j][1];
                s[i][j][2] = __expf(s[i][j][2] - mrow[2*i+1]); sum[2*i+1] += s[i][j][2];
                s[i][j][3] = __expf(s[i][j][3] - mrow[2*i+1]); sum[2*i+1] += s[i][j][3];
            }
#pragma unroll
        for (int t = 0; t < 4; ++t) {
            sum[t] += __shfl_xor_sync(0xffffffffu, sum[t], 1);
            sum[t] += __shfl_xor_sync(0xffffffffu, sum[t], 2);
        }
        if (q == 0) {
#pragma unroll
            for (int t = 0; t < 4; ++t)
                redL[wn * 128 + wm * 32 + t * 8 + g] = sum[t];
        }

        // ---- write P (tf32) to smem; rescale O ----
#pragma unroll
        for (int i = 0; i < 2; ++i)
#pragma unroll
            for (int j = 0; j < 8; ++j) {
                int row = wm * 32 + i * 16 + g;
                int col = wn * 64 + j * 8 + 2 * q;
                *(uint2*)(Ps + row * AP + col) =
                    make_uint2(f2tf(s[i][j][0]), f2tf(s[i][j][1]));
                *(uint2*)(Ps + (row + 8) * AP + col) =
                    make_uint2(f2tf(s[i][j][2]), f2tf(s[i][j][3]));
            }
#pragma unroll
        for (int i = 0; i < 2; ++i)
#pragma unroll
            for (int j = 0; j < 8; ++j) {
                o[i][j][0] *= corr[2*i];   o[i][j][1] *= corr[2*i];
                o[i][j][2] *= corr[2*i+1]; o[i][j][3] *= corr[2*i+1];
            }
        __syncthreads();   // Ps/redL ready; K reads of KVs done

#pragma unroll
        for (int t = 0; t < 4; ++t) {
            int r = wm * 32 + t * 8 + g;
            lrow[t] = lrow[t] * corr[t] + redL[r] + redL[128 + r];
        }

        // ---- stage V tile (rows = d, cols = seq; from pre-transposed Vt) ----
#pragma unroll
        for (int j = 0; j < 16; ++j) {
            int row = (tid >> 5) + 8 * j, qq = tid & 31;
            float4 v = *(const float4*)(Vp + (size_t)row * SEQ + kt + qq * 4);
            *(uint4*)(KVs + row * AP + qq * 4) =
                make_uint4(f2tf(v.x), f2tf(v.y), f2tf(v.z), f2tf(v.w));
        }
        __syncthreads();

        // ---- O += P V ----
#pragma unroll
        for (int ks = 0; ks < 16; ++ks) {
            const int kb = ks * 8;
            unsigned af[2][4], bf[8][2];
#pragma unroll
            for (int i = 0; i < 2; ++i) {
                int r = (wm * 32 + i * 16 + g) * AP + kb + q;
                af[i][0] = Ps[r];       af[i][1] = Ps[r + 8 * AP];
                af[i][2] = Ps[r + 4];   af[i][3] = Ps[r + 8 * AP + 4];
            }
#pragma unroll
            for (int j = 0; j < 8; ++j) {
                int r = (wn * 64 + j * 8 + g) * AP + kb + q;
                bf[j][0] = KVs[r];      bf[j][1] = KVs[r + 4];
            }
#pragma unroll
            for (int i = 0; i < 2; ++i)
#pragma unroll
                for (int j = 0; j < 8; ++j) mma8(o[i][j], af[i], bf[j]);
        }
        __syncthreads();   // KVs/Ps free for next iteration
    }

    // ---- finalize -> AO[B, L, H*D] ----
    const int b = bh >> 4, h = bh & 15;
    float inv[4];
#pragma unroll
    for (int t = 0; t < 4; ++t) inv[t] = 1.f / lrow[t];
#pragma unroll
    for (int i = 0; i < 2; ++i)
#pragma unroll
        for (int j = 0; j < 8; ++j) {
            int r0 = qt * 128 + wm * 32 + i * 16 + g;
            int col = h * HDIM + wn * 64 + j * 8 + 2 * q;
            *(float2*)(AO + (size_t)(b * SEQ + r0) * HIDDEN + col) =
                make_float2(o[i][j][0] * inv[2*i], o[i][j][1] * inv[2*i]);
            *(float2*)(AO + (size_t)(b * SEQ + r0 + 8) * HIDDEN + col) =
                make_float2(o[i][j][2] * inv[2*i+1], o[i][j][3] * inv[2*i+1]);
        }
}

// ============================================================================
// launch
// ============================================================================
extern "C" void kernel_launch(void* const* d_in, const int* in_sizes, int n_in,
                              void* d_out, int out_size)
{
    (void)in_sizes; (void)n_in; (void)out_size;
    const float* x    = (const float*)d_in[0];
    const float* cs   = (const float*)d_in[1];
    const float* sn   = (const float*)d_in[2];
    const float* wqkv = (const float*)d_in[3];
    const float* wout = (const float*)d_in[4];
    float* out = (float*)d_out;

    float *qkv, *q, *k, *vt, *ao;
    cudaGetSymbolAddress((void**)&qkv, g_qkv);
    cudaGetSymbolAddress((void**)&q,   g_q);
    cudaGetSymbolAddress((void**)&k,   g_k);
    cudaGetSymbolAddress((void**)&vt,  g_vt);
    cudaGetSymbolAddress((void**)&ao,  g_ao);

    cudaFuncSetAttribute(attn_tf32,
                         cudaFuncAttributeMaxDynamicSharedMemorySize, ATT_SMEM);

    // 1) qkv = x @ w_qkv^T
    gemm_tf32<<<dim3(NQKV/128, MROWS/128), 256>>>(x, wqkv, qkv, MROWS, NQKV, HIDDEN);
    // 2) RoPE split Q,K + V transpose
    rope_split<<<(BATCH*SEQ*HEADS*64)/256, 256>>>(qkv, cs, sn, q, k);
    transpose_v<<<dim3(SEQ/32, HIDDEN/32, BATCH), dim3(32, 8)>>>(qkv, vt);
    // 3) attention
    attn_tf32<<<dim3(SEQ/128, BATCH*HEADS), 256, ATT_SMEM>>>(q, k, vt, ao);
    // 4) out = ao @ w_out^T
    gemm_tf32<<<dim3(HIDDEN/128, MROWS/128), 256>>>(ao, wout, out, MROWS, HIDDEN, HIDDEN);
}